// round 8
// baseline (speedup 1.0000x reference)
#include <cuda_runtime.h>
#include <cstdint>
#include <math.h>

#define NB 8
#define NT 512
#define NWARP 16   // warps per CTA; 8*16 = 128 global warps, 2 elements each

// ---------------- dynamic smem layout ------------------------------------------
struct __align__(16) SmemLayout {
    float whh[96 * 256];   // this CTA's 96 w_hh rows
    float wih[96 * 256];   // this CTA's 96 w_ih rows
    float enc[20 * 256];
    float h0[256];
    float comb[256];
    float hnew[256];
    float l[32];
    unsigned long long mb_h0;
    unsigned long long mb_comb;
    unsigned long long mb_hnew;
};

// ---------------- helpers ------------------------------------------------------
__device__ __forceinline__ float warp_sum(float v) {
#pragma unroll
    for (int o = 16; o; o >>= 1) v += __shfl_xor_sync(0xffffffffu, v, o);
    return v;
}
__device__ __forceinline__ float warp_max(float v) {
#pragma unroll
    for (int o = 16; o; o >>= 1) v = fmaxf(v, __shfl_xor_sync(0xffffffffu, v, o));
    return v;
}
__device__ __forceinline__ float dot4(float4 a, float4 b) {
    return a.x * b.x + a.y * b.y + a.z * b.z + a.w * b.w;
}
__device__ __forceinline__ uint32_t smem_u32(const void* p) {
    uint32_t a;
    asm("{.reg .u64 t; cvta.to.shared.u64 t,%1; cvt.u32.u64 %0,t;}" : "=r"(a) : "l"(p));
    return a;
}
__device__ __forceinline__ void cp16(void* dst, const void* src) {
    uint32_t d = smem_u32(dst);
    asm volatile("cp.async.cg.shared.global [%0],[%1],16;" :: "r"(d), "l"(src) : "memory");
}
__device__ __forceinline__ void cp_commit() {
    asm volatile("cp.async.commit_group;" ::: "memory");
}
__device__ __forceinline__ void st_cluster(uint32_t laddr, int rank, float v) {
    uint32_t ra;
    asm("mapa.shared::cluster.u32 %0,%1,%2;" : "=r"(ra) : "r"(laddr), "r"(rank));
    asm volatile("st.shared::cluster.f32 [%0],%1;" :: "r"(ra), "f"(v) : "memory");
}
__device__ __forceinline__ void csync() {
    asm volatile("barrier.cluster.arrive.aligned;" ::: "memory");
    asm volatile("barrier.cluster.wait.aligned;" ::: "memory");
}
__device__ __forceinline__ void mbar_init(void* p, unsigned cnt) {
    asm volatile("mbarrier.init.shared.b64 [%0],%1;" :: "r"(smem_u32(p)), "r"(cnt) : "memory");
}
// release-scope arrive on the same mbarrier offset in CTA `rank`
__device__ __forceinline__ void mbar_arrive_rank(void* p, int rank) {
    uint32_t la = smem_u32(p), ra;
    asm("mapa.shared::cluster.u32 %0,%1,%2;" : "=r"(ra) : "r"(la), "r"(rank));
    asm volatile("mbarrier.arrive.release.cluster.shared::cluster.b64 _,[%0];"
                 :: "r"(ra) : "memory");
}
// acquire-wait (parity 0; barriers are re-initialized every launch)
__device__ __forceinline__ void mbar_wait(void* p) {
    uint32_t la = smem_u32(p);
    asm volatile(
        "{\n\t.reg .pred P;\n"
        "W%=:\n\t"
        "mbarrier.try_wait.parity.acquire.cluster.shared::cta.b64 P,[%0],0;\n\t"
        "@!P bra W%=;\n\t}"
        :: "r"(la) : "memory");
}
// fast activations (err ~1e-6, tolerance 1e-3)
__device__ __forceinline__ float fsigmoid(float x) {
    return __fdividef(1.f, 1.f + __expf(-x));
}
__device__ __forceinline__ float ftanh(float x) {
    return 2.f * __fdividef(1.f, 1.f + __expf(-2.f * x)) - 1.f;
}

// ---------------- fused decoder step -------------------------------------------
__global__ void __launch_bounds__(NT, 1) __cluster_dims__(NB, 1, 1)
attn_decoder_fused(const int* __restrict__ inp,
                   const float* __restrict__ hidden,   // [256]
                   const float* __restrict__ enc,      // [20,256]
                   const int* __restrict__ cond,       // [2]
                   const int* __restrict__ is_head,    // [1]
                   const float* __restrict__ emb,      // [29,256]
                   const float* __restrict__ w_l2d,    // [256,264]
                   const float* __restrict__ b_l2d,
                   const float* __restrict__ w_attn,   // [20,512]
                   const float* __restrict__ b_attn,
                   const float* __restrict__ w_comb,   // [256,512]
                   const float* __restrict__ b_comb,
                   const float* __restrict__ w_ih,     // [768,256]
                   const float* __restrict__ w_hh,     // [768,256]
                   const float* __restrict__ b_ih,
                   const float* __restrict__ b_hh,
                   const float* __restrict__ w_out,    // [29,256]
                   const float* __restrict__ b_out,
                   float* __restrict__ out)            // [305]
{
    extern __shared__ SmemLayout sm[];

    const int tid  = threadIdx.x;
    const int lane = tid & 31;
    const int wrp  = tid >> 5;                        // 0..15
    const int bx   = blockIdx.x;
    const int gw   = bx * NWARP + wrp;                // 0..127
    const int e0i  = gw, e1i = gw + 128;

    // ---- t=0: async-stage enc + w_hh + w_ih ---------------------------------
    for (int i = tid; i < 20 * 64; i += NT)
        cp16(&sm->enc[i * 4], enc + i * 4);
#pragma unroll
    for (int i = tid; i < 96 * 64; i += NT) {
        int lr  = i >> 6;
        int col = (i & 63) * 4;
        int g = lr >> 5, e = (lr >> 4) & 1, w = lr & 15;
        int grow = g * 256 + e * 128 + bx * 16 + w;
        cp16(&sm->whh[lr * 256 + col], w_hh + grow * 256 + col);
    }
    cp_commit();                                       // group A
#pragma unroll
    for (int i = tid; i < 96 * 64; i += NT) {
        int lr  = i >> 6;
        int col = (i & 63) * 4;
        int g = lr >> 5, e = (lr >> 4) & 1, w = lr & 15;
        int grow = g * 256 + e * 128 + bx * 16 + w;
        cp16(&sm->wih[lr * 256 + col], w_ih + grow * 256 + col);
    }
    cp_commit();                                       // group B

    const int head = __ldg(is_head);
    const float* erow = emb + __ldg(inp) * 256;

    // per-lane slices + bias prefetch (issued before the init barrier)
    float4 hx0 = __ldg((const float4*)hidden + lane);
    float4 hx1 = __ldg((const float4*)hidden + 32 + lane);
    float4 e0  = __ldg((const float4*)erow + lane);
    float4 e1  = __ldg((const float4*)erow + 32 + lane);
    float  h_e0 = __ldg(hidden + e0i);
    float  h_e1 = __ldg(hidden + e1i);
    float  bh6[6], bi6[6];
#pragma unroll
    for (int r = 0; r < 6; r++) {
        const int o = (r % 3) * 256 + (r < 3 ? e0i : e1i);
        bh6[r] = __ldg(b_hh + o);
        bi6[r] = __ldg(b_ih + o);
    }
    float bc0 = __ldg(b_comb + e0i), bc1 = __ldg(b_comb + e1i);
    float ba1 = __ldg(b_attn + wrp);
    float ba2 = (wrp < 4) ? __ldg(b_attn + 16 + wrp) : 0.f;

    // ---- mbarrier init + publish (hidden under first DRAM loads) ------------
    if (tid == 0) {
        mbar_init(&sm->mb_h0, NB);
        mbar_init(&sm->mb_comb, NB);
        mbar_init(&sm->mb_hnew, NB);
    }
    __syncthreads();
    csync();                                           // publish inits

    // ---- P1: h0 rows e0i,e1i (head path) + emb-half partials ----------------
    float h00 = 0.f, h01 = 0.f;
    if (head) {
        int c0 = __ldg(cond), c1 = __ldg(cond + 1);
#pragma unroll
        for (int e = 0; e < 2; e++) {
            const int o = e ? e1i : e0i;
            const float* wr = w_l2d + o * 264;
            float s = dot4(__ldg((const float4*)wr + lane), hx0) +
                      dot4(__ldg((const float4*)(wr + 128) + lane), hx1);
            if (lane < 8) {
                float xv = (lane == c0 || lane == 4 + c1) ? 1.f : 0.f;
                s += wr[256 + lane] * xv;
            }
            s = warp_sum(s) + __ldg(b_l2d + o);
            if (e) h01 = s; else h00 = s;
        }
        if (lane < 8)       st_cluster(smem_u32(&sm->h0[e0i]), lane, h00);
        else if (lane < 16) st_cluster(smem_u32(&sm->h0[e1i]), lane - 8, h01);
    }
    __syncthreads();
    if (tid == 0) {
#pragma unroll
        for (int r = 0; r < NB; r++) mbar_arrive_rank(&sm->mb_h0, r);
    }
    // comb emb-half partials + attn emb-half (overlap with h0 propagation)
    const float* wc0 = w_comb + e0i * 512;
    const float* wc1 = w_comb + e1i * 512;
    float ce0 = dot4(__ldg((const float4*)wc0 + lane), e0) +
                dot4(__ldg((const float4*)wc0 + 32 + lane), e1);
    float ce1 = dot4(__ldg((const float4*)wc1 + lane), e0) +
                dot4(__ldg((const float4*)wc1 + 32 + lane), e1);
    float ae1, ae2 = 0.f;
    {
        const float* wa = w_attn + wrp * 512;
        ae1 = dot4(__ldg((const float4*)wa + lane), e0) +
              dot4(__ldg((const float4*)wa + 32 + lane), e1);
        if (wrp < 4) {
            const float* wb = w_attn + (16 + wrp) * 512;
            ae2 = dot4(__ldg((const float4*)wb + lane), e0) +
                  dot4(__ldg((const float4*)wb + 32 + lane), e1);
        }
    }
    // register-prefetch P2 small weights
    float4 wa1_0, wa1_1, wa2_0, wa2_1;
    {
        const float* wa = w_attn + wrp * 512 + 256;
        wa1_0 = __ldg((const float4*)wa + lane);
        wa1_1 = __ldg((const float4*)wa + 32 + lane);
        if (wrp < 4) {
            const float* wb = w_attn + (16 + wrp) * 512 + 256;
            wa2_0 = __ldg((const float4*)wb + lane);
            wa2_1 = __ldg((const float4*)wb + 32 + lane);
        }
    }
    float4 wch0_0 = __ldg((const float4*)(wc0 + 256) + lane);
    float4 wch0_1 = __ldg((const float4*)(wc0 + 256) + 32 + lane);
    float4 wch1_0 = __ldg((const float4*)(wc1 + 256) + lane);
    float4 wch1_1 = __ldg((const float4*)(wc1 + 256) + 32 + lane);
    asm volatile("cp.async.wait_group 1;" ::: "memory");   // enc + whh done
    mbar_wait(&sm->mb_h0);                                 // ---- sync 1

    // ---- P2: gh from SMEM + attn logits + softmax + attn_applied + comb -----
    float4 x0, x1;
    if (head) { x0 = *((const float4*)sm->h0 + lane); x1 = *((const float4*)sm->h0 + 32 + lane); }
    else      { x0 = hx0; x1 = hx1; }
    float ghv[6];
#pragma unroll
    for (int r = 0; r < 6; r++) {
        const int g = r % 3, e = r / 3;
        const float* w = &sm->whh[((g * 2 + e) * 16 + wrp) * 256];
        ghv[r] = warp_sum(dot4(*((const float4*)w + lane), x0) +
                          dot4(*((const float4*)w + 32 + lane), x1)) + bh6[r];
    }
    {
        float s = warp_sum(ae1 + dot4(wa1_0, x0) + dot4(wa1_1, x1));
        if (lane == 0) sm->l[wrp] = s + ba1;
        if (wrp < 4) {
            float s2 = warp_sum(ae2 + dot4(wa2_0, x0) + dot4(wa2_1, x1));
            if (lane == 0) sm->l[16 + wrp] = s2 + ba2;
        }
    }
    __syncthreads();                                   // logits ready (CTA-local)
    {
        float v = (lane < 20) ? sm->l[lane] : -1e30f;
        float m = warp_max(v);
        float ex = (lane < 20) ? __expf(v - m) : 0.f;
        float sum = warp_sum(ex);
        float w = __fdividef(ex, sum);
        if (gw == 0 && lane < 20) out[285 + lane] = w;
        float4 a0 = {0.f,0.f,0.f,0.f}, a1 = {0.f,0.f,0.f,0.f};
#pragma unroll
        for (int l = 0; l < 20; l++) {
            float wl = __shfl_sync(0xffffffffu, w, l);
            float4 q0 = *((const float4*)(sm->enc + l * 256) + lane);
            float4 q1 = *((const float4*)(sm->enc + l * 256) + 32 + lane);
            a0.x += wl*q0.x; a0.y += wl*q0.y; a0.z += wl*q0.z; a0.w += wl*q0.w;
            a1.x += wl*q1.x; a1.y += wl*q1.y; a1.z += wl*q1.z; a1.w += wl*q1.w;
        }
        float sc0 = warp_sum(ce0 + dot4(wch0_0, a0) + dot4(wch0_1, a1));
        float sc1 = warp_sum(ce1 + dot4(wch1_0, a0) + dot4(wch1_1, a1));
        sc0 = fmaxf(sc0 + bc0, 0.f);
        sc1 = fmaxf(sc1 + bc1, 0.f);
        if (lane < 8)       st_cluster(smem_u32(&sm->comb[e0i]), lane, sc0);
        else if (lane < 16) st_cluster(smem_u32(&sm->comb[e1i]), lane - 8, sc1);
    }
    __syncthreads();
    if (tid == 0) {
#pragma unroll
        for (int r = 0; r < NB; r++) mbar_arrive_rank(&sm->mb_comb, r);
    }
    asm volatile("cp.async.wait_group 0;" ::: "memory");   // wih done
    mbar_wait(&sm->mb_comb);                               // ---- sync 2

    // ---- P3: gi from SMEM + fused GRU (gh in registers) ---------------------
    {
        float4 c0 = *((const float4*)sm->comb + lane);
        float4 c1 = *((const float4*)sm->comb + 32 + lane);
        float gi[6];
#pragma unroll
        for (int r = 0; r < 6; r++) {
            const int g = r % 3, e = r / 3;
            const float* w = &sm->wih[((g * 2 + e) * 16 + wrp) * 256];
            gi[r] = warp_sum(dot4(*((const float4*)w + lane), c0) +
                             dot4(*((const float4*)w + 32 + lane), c1)) + bi6[r];
        }
#pragma unroll
        for (int e = 0; e < 2; e++) {
            const int o = e ? e1i : e0i;
            float h0o = head ? (e ? h01 : h00) : (e ? h_e1 : h_e0);
            float r = fsigmoid(gi[e * 3 + 0] + ghv[e * 3 + 0]);
            float z = fsigmoid(gi[e * 3 + 1] + ghv[e * 3 + 1]);
            float n = ftanh(gi[e * 3 + 2] + r * ghv[e * 3 + 2]);
            float h = (1.f - z) * n + z * h0o;
            if (lane == 0) {
                st_cluster(smem_u32(&sm->hnew[o]), 0, h);   // to CTA0 only
                out[29 + o] = h;
            }
        }
    }
    __syncthreads();
    if (tid == 0) mbar_arrive_rank(&sm->mb_hnew, 0);       // signal CTA0
    if (bx != 0) return;                                   // CTAs 1-7 exit

    // register-prefetch P4 weights while waiting
    float4 wo[2][2]; float bo[2];
#pragma unroll
    for (int r = 0; r < 2; r++) {
        const int o = wrp * 2 + r;
        if (o < 29) {
            const float* w = w_out + o * 256;
            wo[r][0] = __ldg((const float4*)w + lane);
            wo[r][1] = __ldg((const float4*)w + 32 + lane);
            bo[r] = __ldg(b_out + o);
        }
    }
    mbar_wait(&sm->mb_hnew);                               // ---- sync 3

    // ---- P4 (CTA0): output logits + log_softmax -----------------------------
    {
        float4 h0x = *((const float4*)sm->hnew + lane);
        float4 h1x = *((const float4*)sm->hnew + 32 + lane);
#pragma unroll
        for (int r = 0; r < 2; r++) {
            const int o = wrp * 2 + r;
            if (o < 29) {
                float s = warp_sum(dot4(wo[r][0], h0x) + dot4(wo[r][1], h1x)) + bo[r];
                if (lane == 0) sm->l[o] = s;
            }
        }
    }
    __syncthreads();
    if (wrp == 0) {
        float v = (lane < 29) ? sm->l[lane] : -1e30f;
        float m = warp_max(v);
        float e = (lane < 29) ? __expf(v - m) : 0.f;
        float sum = warp_sum(e);
        float ls = __logf(sum);
        if (lane < 29) out[lane] = v - m - ls;
    }
}

// ---------------- launch --------------------------------------------------------
extern "C" void kernel_launch(void* const* d_in, const int* in_sizes, int n_in,
                              void* d_out, int out_size) {
    (void)in_sizes; (void)n_in; (void)out_size;
    cudaFuncSetAttribute(attn_decoder_fused,
                         cudaFuncAttributeMaxDynamicSharedMemorySize,
                         (int)sizeof(SmemLayout));
    attn_decoder_fused<<<NB, NT, sizeof(SmemLayout)>>>(
        (const int*)d_in[0],  (const float*)d_in[1], (const float*)d_in[2],
        (const int*)d_in[3],  (const int*)d_in[4],   (const float*)d_in[5],
        (const float*)d_in[6],(const float*)d_in[7], (const float*)d_in[8],
        (const float*)d_in[9],(const float*)d_in[10],(const float*)d_in[11],
        (const float*)d_in[12],(const float*)d_in[13],(const float*)d_in[14],
        (const float*)d_in[15],(const float*)d_in[16],(const float*)d_in[17],
        (float*)d_out);
}

// round 9
// speedup vs baseline: 1.3145x; 1.3145x over previous
#include <cuda_runtime.h>
#include <cstdint>
#include <math.h>

// ---------------- helpers ------------------------------------------------------
__device__ __forceinline__ float warp_sum(float v) {
#pragma unroll
    for (int o = 16; o; o >>= 1) v += __shfl_xor_sync(0xffffffffu, v, o);
    return v;
}
__device__ __forceinline__ float warp_max(float v) {
#pragma unroll
    for (int o = 16; o; o >>= 1) v = fmaxf(v, __shfl_xor_sync(0xffffffffu, v, o));
    return v;
}
__device__ __forceinline__ float dot4(float4 a, float4 b) {
    return a.x * b.x + a.y * b.y + a.z * b.z + a.w * b.w;
}
__device__ __forceinline__ uint32_t smem_u32(const void* p) {
    uint32_t a;
    asm("{.reg .u64 t; cvta.to.shared.u64 t,%1; cvt.u32.u64 %0,t;}" : "=r"(a) : "l"(p));
    return a;
}
// store 4B to the same smem offset in CTA `rank` of the cluster
__device__ __forceinline__ void st_cluster(uint32_t laddr, int rank, float v) {
    uint32_t ra;
    asm("mapa.shared::cluster.u32 %0,%1,%2;" : "=r"(ra) : "r"(laddr), "r"(rank));
    asm volatile("st.shared::cluster.f32 [%0],%1;" :: "r"(ra), "f"(v) : "memory");
}
// HW cluster barrier (release/acquire at cluster scope)
__device__ __forceinline__ void csync() {
    asm volatile("barrier.cluster.arrive.aligned;" ::: "memory");
    asm volatile("barrier.cluster.wait.aligned;" ::: "memory");
}

// ---------------- fused decoder step (templated on cluster geometry) -----------
template <int CTAS, int NTHR>
__global__ void __launch_bounds__(NTHR, 1)
decoder_k(const int* __restrict__ inp,
          const float* __restrict__ hidden,   // [256]
          const float* __restrict__ enc,      // [20,256]
          const int* __restrict__ cond,       // [2]
          const int* __restrict__ is_head,    // [1]
          const float* __restrict__ emb,      // [29,256]
          const float* __restrict__ w_l2d,    // [256,264]
          const float* __restrict__ b_l2d,
          const float* __restrict__ w_attn,   // [20,512]
          const float* __restrict__ b_attn,
          const float* __restrict__ w_comb,   // [256,512]
          const float* __restrict__ b_comb,
          const float* __restrict__ w_ih,     // [768,256]
          const float* __restrict__ w_hh,     // [768,256]
          const float* __restrict__ b_ih,
          const float* __restrict__ b_hh,
          const float* __restrict__ w_out,    // [29,256]
          const float* __restrict__ b_out,
          float* __restrict__ out)            // [305]
{
    constexpr int NW = NTHR / 32;             // warps per CTA; CTAS*NW == 128
    __shared__ __align__(16) float sEnc[20 * 256];
    __shared__ __align__(16) float sH0[256];
    __shared__ __align__(16) float sComb[256];
    __shared__ __align__(16) float sHnew[256];
    __shared__ float sLog[32];
    __shared__ float sOut[32];

    const int tid  = threadIdx.x;
    const int lane = tid & 31;
    const int wrp  = tid >> 5;
    const int bx   = blockIdx.x;
    const int gw   = bx * NW + wrp;           // 0..127
    const int e0i  = gw, e1i = gw + 128;

    // ---- stage enc into smem ------------------------------------------------
    for (int i = tid; i < 20 * 64; i += NTHR)
        ((float4*)sEnc)[i] = __ldg((const float4*)enc + i);

    const int head = __ldg(is_head);
    const float* erow = emb + __ldg(inp) * 256;

    float4 hx0 = __ldg((const float4*)hidden + lane);
    float4 hx1 = __ldg((const float4*)hidden + 32 + lane);
    float4 e0  = __ldg((const float4*)erow + lane);
    float4 e1  = __ldg((const float4*)erow + 32 + lane);
    float  h_e0 = __ldg(hidden + e0i);
    float  h_e1 = __ldg(hidden + e1i);
    float  bh6[6], bi6[6];                    // idx = e*3+g
#pragma unroll
    for (int r = 0; r < 6; r++) {
        const int o = (r % 3) * 256 + (r < 3 ? e0i : e1i);
        bh6[r] = __ldg(b_hh + o);
        bi6[r] = __ldg(b_ih + o);
    }
    float bc0 = __ldg(b_comb + e0i), bc1 = __ldg(b_comb + e1i);

    // ---- P1: h0 rows (head path) + emb-half partials ------------------------
    float h00 = 0.f, h01 = 0.f;
    if (head) {
        int c0 = __ldg(cond), c1 = __ldg(cond + 1);
#pragma unroll
        for (int e = 0; e < 2; e++) {
            const int o = e ? e1i : e0i;
            const float* wr = w_l2d + o * 264;
            float s = dot4(__ldg((const float4*)wr + lane), hx0) +
                      dot4(__ldg((const float4*)(wr + 128) + lane), hx1);
            if (lane < 8) {
                float xv = (lane == c0 || lane == 4 + c1) ? 1.f : 0.f;
                s += wr[256 + lane] * xv;
            }
            s = warp_sum(s) + __ldg(b_l2d + o);
            if (e) h01 = s; else h00 = s;
        }
        if (lane < CTAS)          st_cluster(smem_u32(&sH0[e0i]), lane, h00);
        else if (lane < 2 * CTAS) st_cluster(smem_u32(&sH0[e1i]), lane - CTAS, h01);
    }
    // comb emb-half partials
    const float* wc0 = w_comb + e0i * 512;
    const float* wc1 = w_comb + e1i * 512;
    float ce0 = dot4(__ldg((const float4*)wc0 + lane), e0) +
                dot4(__ldg((const float4*)wc0 + 32 + lane), e1);
    float ce1 = dot4(__ldg((const float4*)wc1 + lane), e0) +
                dot4(__ldg((const float4*)wc1 + 32 + lane), e1);
    // distributed attention row prefetch (warp gw<20 owns row gw)
    float4 wa[4]; float ba = 0.f;
    if (gw < 20) {
        const float* w = w_attn + gw * 512;
#pragma unroll
        for (int k = 0; k < 4; k++) wa[k] = __ldg((const float4*)w + k * 32 + lane);
        ba = __ldg(b_attn + gw);
    }
    // prefetch P2 weights: w_hh rows + comb c-half
    float4 wh[6][2];
#pragma unroll
    for (int r = 0; r < 6; r++) {
        const int o = (r % 3) * 256 + (r < 3 ? e0i : e1i);
        const float* w = w_hh + o * 256;
        wh[r][0] = __ldg((const float4*)w + lane);
        wh[r][1] = __ldg((const float4*)w + 32 + lane);
    }
    float4 wch0_0 = __ldg((const float4*)(wc0 + 256) + lane);
    float4 wch0_1 = __ldg((const float4*)(wc0 + 256) + 32 + lane);
    float4 wch1_0 = __ldg((const float4*)(wc1 + 256) + lane);
    float4 wch1_1 = __ldg((const float4*)(wc1 + 256) + 32 + lane);
    csync();                                                  // ---- cs1 (h0)

    // ---- P2: gh (registers) + distributed attn logits -----------------------
    float4 x0, x1;
    if (head) { x0 = *((const float4*)sH0 + lane); x1 = *((const float4*)sH0 + 32 + lane); }
    else      { x0 = hx0; x1 = hx1; }
    float ghv[6];
#pragma unroll
    for (int r = 0; r < 6; r++)
        ghv[r] = warp_sum(dot4(wh[r][0], x0) + dot4(wh[r][1], x1)) + bh6[r];
    if (gw < 20) {
        float s = warp_sum(dot4(wa[0], e0) + dot4(wa[1], e1) +
                           dot4(wa[2], x0) + dot4(wa[3], x1)) + ba;
        if (lane < CTAS) st_cluster(smem_u32(&sLog[gw]), lane, s);
    }
    // prefetch P4 weights (w_ih rows)
    float4 wi[6][2];
#pragma unroll
    for (int r = 0; r < 6; r++) {
        const int o = (r % 3) * 256 + (r < 3 ? e0i : e1i);
        const float* w = w_ih + o * 256;
        wi[r][0] = __ldg((const float4*)w + lane);
        wi[r][1] = __ldg((const float4*)w + 32 + lane);
    }
    csync();                                                  // ---- cs2 (logits)

    // ---- P3: softmax (warp-redundant) + attn_applied + comb -----------------
    {
        float v = (lane < 20) ? sLog[lane] : -1e30f;
        float m = warp_max(v);
        float ex = (lane < 20) ? expf(v - m) : 0.f;
        float sum = warp_sum(ex);
        float w = ex / sum;
        if (gw == 0 && lane < 20) out[285 + lane] = w;
        float4 a0 = {0.f,0.f,0.f,0.f}, a1 = {0.f,0.f,0.f,0.f};
#pragma unroll
        for (int l = 0; l < 20; l++) {
            float wl = __shfl_sync(0xffffffffu, w, l);
            float4 q0 = *((const float4*)(sEnc + l * 256) + lane);
            float4 q1 = *((const float4*)(sEnc + l * 256) + 32 + lane);
            a0.x += wl*q0.x; a0.y += wl*q0.y; a0.z += wl*q0.z; a0.w += wl*q0.w;
            a1.x += wl*q1.x; a1.y += wl*q1.y; a1.z += wl*q1.z; a1.w += wl*q1.w;
        }
        float sc0 = warp_sum(ce0 + dot4(wch0_0, a0) + dot4(wch0_1, a1));
        float sc1 = warp_sum(ce1 + dot4(wch1_0, a0) + dot4(wch1_1, a1));
        sc0 = fmaxf(sc0 + bc0, 0.f);
        sc1 = fmaxf(sc1 + bc1, 0.f);
        if (lane < CTAS)          st_cluster(smem_u32(&sComb[e0i]), lane, sc0);
        else if (lane < 2 * CTAS) st_cluster(smem_u32(&sComb[e1i]), lane - CTAS, sc1);
    }
    csync();                                                  // ---- cs3 (comb)

    // ---- P4: gi + fused GRU -------------------------------------------------
    {
        float4 c0 = *((const float4*)sComb + lane);
        float4 c1 = *((const float4*)sComb + 32 + lane);
        float gi[6];
#pragma unroll
        for (int r = 0; r < 6; r++)
            gi[r] = warp_sum(dot4(wi[r][0], c0) + dot4(wi[r][1], c1)) + bi6[r];
#pragma unroll
        for (int e = 0; e < 2; e++) {
            const int o = e ? e1i : e0i;
            float h0o = head ? (e ? h01 : h00) : (e ? h_e1 : h_e0);
            float r = 1.f / (1.f + expf(-(gi[e * 3 + 0] + ghv[e * 3 + 0])));
            float z = 1.f / (1.f + expf(-(gi[e * 3 + 1] + ghv[e * 3 + 1])));
            float n = tanhf(gi[e * 3 + 2] + r * ghv[e * 3 + 2]);
            float h = (1.f - z) * n + z * h0o;
            if (lane == 0) {
                st_cluster(smem_u32(&sHnew[o]), 0, h);        // to CTA0 only
                out[29 + o] = h;
            }
        }
    }
    // prefetch P5 weights (CTA0)
    float4 wo[4][2]; float bo[4];
    if (bx == 0) {
#pragma unroll
        for (int r = 0; r < 4; r++) {
            const int o = wrp + r * NW;
            if (o < 29) {
                const float* w = w_out + o * 256;
                wo[r][0] = __ldg((const float4*)w + lane);
                wo[r][1] = __ldg((const float4*)w + 32 + lane);
                bo[r] = __ldg(b_out + o);
            }
        }
    }
    csync();                                                  // ---- cs4 (hnew)
    if (bx != 0) return;

    // ---- P5 (CTA0): output logits + log_softmax -----------------------------
    {
        float4 H0 = *((const float4*)sHnew + lane);
        float4 H1 = *((const float4*)sHnew + 32 + lane);
#pragma unroll
        for (int r = 0; r < 4; r++) {
            const int o = wrp + r * NW;
            if (o < 29) {
                float s = warp_sum(dot4(wo[r][0], H0) + dot4(wo[r][1], H1)) + bo[r];
                if (lane == 0) sOut[o] = s;
            }
        }
    }
    __syncthreads();
    if (wrp == 0) {
        float v = (lane < 29) ? sOut[lane] : -1e30f;
        float m = warp_max(v);
        float e = (lane < 29) ? expf(v - m) : 0.f;
        float sum = warp_sum(e);
        float ls = logf(sum);
        if (lane < 29) out[lane] = v - m - ls;
    }
}

// ---------------- launch --------------------------------------------------------
extern "C" void kernel_launch(void* const* d_in, const int* in_sizes, int n_in,
                              void* d_out, int out_size) {
    (void)in_sizes; (void)n_in; (void)out_size;
    const int*   inp     = (const int*)  d_in[0];
    const float* hidden  = (const float*)d_in[1];
    const float* enc     = (const float*)d_in[2];
    const int*   cond    = (const int*)  d_in[3];
    const int*   is_head = (const int*)  d_in[4];
    const float* emb     = (const float*)d_in[5];
    const float* w_l2d   = (const float*)d_in[6];
    const float* b_l2d   = (const float*)d_in[7];
    const float* w_attn  = (const float*)d_in[8];
    const float* b_attn  = (const float*)d_in[9];
    const float* w_comb  = (const float*)d_in[10];
    const float* b_comb  = (const float*)d_in[11];
    const float* w_ih    = (const float*)d_in[12];
    const float* w_hh    = (const float*)d_in[13];
    const float* b_ih    = (const float*)d_in[14];
    const float* b_hh    = (const float*)d_in[15];
    const float* w_out   = (const float*)d_in[16];
    const float* b_out   = (const float*)d_in[17];
    float* out = (float*)d_out;

    // Preferred: 16-CTA non-portable cluster (2x SMs -> 2x aggregate per-SM BW)
    cudaFuncSetAttribute(decoder_k<16, 256>,
                         cudaFuncAttributeNonPortableClusterSizeAllowed, 1);

    cudaLaunchAttribute at[1];
    at[0].id = cudaLaunchAttributeClusterDimension;
    at[0].val.clusterDim = {16, 1, 1};

    cudaLaunchConfig_t cfg16 = {};
    cfg16.gridDim  = {16, 1, 1};
    cfg16.blockDim = {256, 1, 1};
    cfg16.attrs = at;
    cfg16.numAttrs = 1;

    int maxc = 0;
    cudaError_t qerr = cudaOccupancyMaxActiveClusters(&maxc, decoder_k<16, 256>, &cfg16);
    if (qerr == cudaSuccess && maxc >= 1) {
        cudaLaunchKernelEx(&cfg16, decoder_k<16, 256>,
                           inp, hidden, enc, cond, is_head, emb,
                           w_l2d, b_l2d, w_attn, b_attn, w_comb, b_comb,
                           w_ih, w_hh, b_ih, b_hh, w_out, b_out, out);
    } else {
        (void)cudaGetLastError();   // clear sticky query error
        cudaLaunchAttribute at8[1];
        at8[0].id = cudaLaunchAttributeClusterDimension;
        at8[0].val.clusterDim = {8, 1, 1};
        cudaLaunchConfig_t cfg8 = {};
        cfg8.gridDim  = {8, 1, 1};
        cfg8.blockDim = {512, 1, 1};
        cfg8.attrs = at8;
        cfg8.numAttrs = 1;
        cudaLaunchKernelEx(&cfg8, decoder_k<8, 512>,
                           inp, hidden, enc, cond, is_head, emb,
                           w_l2d, b_l2d, w_attn, b_attn, w_comb, b_comb,
                           w_ih, w_hh, b_ih, b_hh, w_out, b_out, out);
    }
}

// round 10
// speedup vs baseline: 1.3409x; 1.0201x over previous
#include <cuda_runtime.h>
#include <cstdint>
#include <math.h>

#define CTAS 16
#define NTHR 256
#define NW   8      // warps per CTA; CTAS*NW = 128 global warps, 2 elems/warp

// ---------------- dynamic smem layout ------------------------------------------
struct __align__(16) Smem {
    float wl2d[2 * NW * 264];   // 16 rows x 264          (16896 B)
    float whh [6 * NW * 256];   // 48 rows x 256          (49152 B)
    float wih [6 * NW * 256];   // 48 rows x 256          (49152 B)
    float wcmb[2 * NW * 512];   // 16 rows x 512          (32768 B)
    float enc [20 * 256];       //                        (20480 B)
    float h0[256];
    float comb[256];
    float hnew[256];
    float logit[32];
    float olog[32];
    unsigned long long mb1, mb2;
};

// ---------------- helpers ------------------------------------------------------
__device__ __forceinline__ float warp_sum(float v) {
#pragma unroll
    for (int o = 16; o; o >>= 1) v += __shfl_xor_sync(0xffffffffu, v, o);
    return v;
}
__device__ __forceinline__ float warp_max(float v) {
#pragma unroll
    for (int o = 16; o; o >>= 1) v = fmaxf(v, __shfl_xor_sync(0xffffffffu, v, o));
    return v;
}
__device__ __forceinline__ float dot4(float4 a, float4 b) {
    return a.x * b.x + a.y * b.y + a.z * b.z + a.w * b.w;
}
__device__ __forceinline__ uint32_t smem_u32(const void* p) {
    uint32_t a;
    asm("{.reg .u64 t; cvta.to.shared.u64 t,%1; cvt.u32.u64 %0,t;}" : "=r"(a) : "l"(p));
    return a;
}
__device__ __forceinline__ void st_cluster(uint32_t laddr, int rank, float v) {
    uint32_t ra;
    asm("mapa.shared::cluster.u32 %0,%1,%2;" : "=r"(ra) : "r"(laddr), "r"(rank));
    asm volatile("st.shared::cluster.f32 [%0],%1;" :: "r"(ra), "f"(v) : "memory");
}
__device__ __forceinline__ void csync() {
    asm volatile("barrier.cluster.arrive.aligned;" ::: "memory");
    asm volatile("barrier.cluster.wait.aligned;" ::: "memory");
}
__device__ __forceinline__ void mbar_init(void* p, unsigned cnt) {
    asm volatile("mbarrier.init.shared.b64 [%0],%1;" :: "r"(smem_u32(p)), "r"(cnt) : "memory");
}
__device__ __forceinline__ void mbar_expect(void* p, unsigned bytes) {
    asm volatile("mbarrier.arrive.expect_tx.shared.b64 _,[%0],%1;"
                 :: "r"(smem_u32(p)), "r"(bytes) : "memory");
}
__device__ __forceinline__ void bulk_g2s(void* dst, const void* src, unsigned bytes, void* mbar) {
    asm volatile("cp.async.bulk.shared::cta.global.mbarrier::complete_tx::bytes [%0],[%1],%2,[%3];"
                 :: "r"(smem_u32(dst)), "l"(src), "r"(bytes), "r"(smem_u32(mbar)) : "memory");
}
__device__ __forceinline__ void mbar_wait(void* p) {
    uint32_t la = smem_u32(p);
    asm volatile(
        "{\n\t.reg .pred P;\n"
        "W%=:\n\t"
        "mbarrier.try_wait.parity.shared.b64 P,[%0],0;\n\t"
        "@!P bra W%=;\n\t}"
        :: "r"(la) : "memory");
}

// ---------------- fused decoder step -------------------------------------------
__global__ void __launch_bounds__(NTHR, 1)
decoder_k(const int* __restrict__ inp,
          const float* __restrict__ hidden,   // [256]
          const float* __restrict__ enc,      // [20,256]
          const int* __restrict__ cond,       // [2]
          const int* __restrict__ is_head,    // [1]
          const float* __restrict__ emb,      // [29,256]
          const float* __restrict__ w_l2d,    // [256,264]
          const float* __restrict__ b_l2d,
          const float* __restrict__ w_attn,   // [20,512]
          const float* __restrict__ b_attn,
          const float* __restrict__ w_comb,   // [256,512]
          const float* __restrict__ b_comb,
          const float* __restrict__ w_ih,     // [768,256]
          const float* __restrict__ w_hh,     // [768,256]
          const float* __restrict__ b_ih,
          const float* __restrict__ b_hh,
          const float* __restrict__ w_out,    // [29,256]
          const float* __restrict__ b_out,
          float* __restrict__ out)            // [305]
{
    extern __shared__ Smem sm[];

    const int tid  = threadIdx.x;
    const int lane = tid & 31;
    const int wrp  = tid >> 5;                // 0..7
    const int bx   = blockIdx.x;
    const int gw   = bx * NW + wrp;           // 0..127
    const int e0i  = gw, e1i = gw + 128;

    // ---- t=0: mbarrier init + all bulk copies via TMA pipe ------------------
    if (tid == 0) { mbar_init(&sm->mb1, 1); mbar_init(&sm->mb2, 1); }
    __syncthreads();
    if (tid == 0) {
        const unsigned tx1 = 20480u + 2u * 8448u + 6u * 8192u + 2u * 16384u;  // 119296
        mbar_expect(&sm->mb1, tx1);
        bulk_g2s(sm->enc, enc, 20480u, &sm->mb1);
#pragma unroll
        for (int e = 0; e < 2; e++)
            bulk_g2s(&sm->wl2d[e * NW * 264], w_l2d + (e * 128 + bx * NW) * 264,
                     NW * 264 * 4u, &sm->mb1);
#pragma unroll
        for (int c = 0; c < 6; c++) {         // c = g*2+e
            int g = c >> 1, e = c & 1;
            bulk_g2s(&sm->whh[c * NW * 256], w_hh + (g * 256 + e * 128 + bx * NW) * 256,
                     NW * 256 * 4u, &sm->mb1);
        }
#pragma unroll
        for (int e = 0; e < 2; e++)
            bulk_g2s(&sm->wcmb[e * NW * 512], w_comb + (e * 128 + bx * NW) * 512,
                     NW * 512 * 4u, &sm->mb1);
        mbar_expect(&sm->mb2, 6u * 8192u);
#pragma unroll
        for (int c = 0; c < 6; c++) {
            int g = c >> 1, e = c & 1;
            bulk_g2s(&sm->wih[c * NW * 256], w_ih + (g * 256 + e * 128 + bx * NW) * 256,
                     NW * 256 * 4u, &sm->mb2);
        }
    }

    // ---- small LDGs (overlap with bulk flight) ------------------------------
    const int head = __ldg(is_head);
    const float* erow = emb + __ldg(inp) * 256;
    float4 hx0 = __ldg((const float4*)hidden + lane);
    float4 hx1 = __ldg((const float4*)hidden + 32 + lane);
    float4 e0  = __ldg((const float4*)erow + lane);
    float4 e1  = __ldg((const float4*)erow + 32 + lane);
    float  h_e0 = __ldg(hidden + e0i);
    float  h_e1 = __ldg(hidden + e1i);
    float  bh6[6], bi6[6];
#pragma unroll
    for (int r = 0; r < 6; r++) {
        const int o = (r % 3) * 256 + (r < 3 ? e0i : e1i);
        bh6[r] = __ldg(b_hh + o);
        bi6[r] = __ldg(b_ih + o);
    }
    float bc0 = __ldg(b_comb + e0i), bc1 = __ldg(b_comb + e1i);
    float bl0 = __ldg(b_l2d + e0i),  bl1 = __ldg(b_l2d + e1i);
    // distributed attention row (warp gw<20 owns row gw) via LDG
    float4 wa[4]; float ba = 0.f;
    if (gw < 20) {
        const float* w = w_attn + gw * 512;
#pragma unroll
        for (int k = 0; k < 4; k++) wa[k] = __ldg((const float4*)w + k * 32 + lane);
        ba = __ldg(b_attn + gw);
    }
    int c0i = __ldg(cond), c1i = __ldg(cond + 1);

    mbar_wait(&sm->mb1);                                     // bulk group 1 landed

    // ---- P1: h0 rows (head path, weights from smem) -------------------------
    float h00 = 0.f, h01 = 0.f;
    if (head) {
#pragma unroll
        for (int e = 0; e < 2; e++) {
            const float* wr = &sm->wl2d[(e * NW + wrp) * 264];
            float s = dot4(*((const float4*)wr + lane), e ? hx0 : hx0) +
                      dot4(*((const float4*)(wr + 128) + lane), hx1);
            if (lane < 8) {
                float xv = (lane == c0i || lane == 4 + c1i) ? 1.f : 0.f;
                s += wr[256 + lane] * xv;
            }
            s = warp_sum(s) + (e ? bl1 : bl0);
            if (e) h01 = s; else h00 = s;
        }
        if (lane < 16) st_cluster(smem_u32(&sm->h0[e0i]), lane, h00);
        else           st_cluster(smem_u32(&sm->h0[e1i]), lane - 16, h01);
    }
    // comb emb-half partials from smem
    const float* wcr0 = &sm->wcmb[wrp * 512];
    const float* wcr1 = &sm->wcmb[(NW + wrp) * 512];
    float ce0 = dot4(*((const float4*)wcr0 + lane), e0) +
                dot4(*((const float4*)wcr0 + 32 + lane), e1);
    float ce1 = dot4(*((const float4*)wcr1 + lane), e0) +
                dot4(*((const float4*)wcr1 + 32 + lane), e1);
    csync();                                                  // ---- cs1 (h0)

    // ---- P2: gh (smem weights -> registers) + distributed attn logits -------
    float4 x0, x1;
    if (head) { x0 = *((const float4*)sm->h0 + lane); x1 = *((const float4*)sm->h0 + 32 + lane); }
    else      { x0 = hx0; x1 = hx1; }
    float ghv[6];
#pragma unroll
    for (int r = 0; r < 6; r++) {
        const int g = r % 3, e = r / 3;
        const float* w = &sm->whh[((g * 2 + e) * NW + wrp) * 256];
        ghv[r] = warp_sum(dot4(*((const float4*)w + lane), x0) +
                          dot4(*((const float4*)w + 32 + lane), x1)) + bh6[r];
    }
    if (gw < 20) {
        float s = warp_sum(dot4(wa[0], e0) + dot4(wa[1], e1) +
                           dot4(wa[2], x0) + dot4(wa[3], x1)) + ba;
        if (lane < CTAS) st_cluster(smem_u32(&sm->logit[gw]), lane, s);
    }
    csync();                                                  // ---- cs2 (logits)

    // ---- P3: softmax (warp-redundant) + attn_applied + comb -----------------
    {
        float v = (lane < 20) ? sm->logit[lane] : -1e30f;
        float m = warp_max(v);
        float ex = (lane < 20) ? expf(v - m) : 0.f;
        float sum = warp_sum(ex);
        float w = ex / sum;
        if (gw == 0 && lane < 20) out[285 + lane] = w;
        float4 a0 = {0.f,0.f,0.f,0.f}, a1 = {0.f,0.f,0.f,0.f};
#pragma unroll
        for (int l = 0; l < 20; l++) {
            float wl = __shfl_sync(0xffffffffu, w, l);
            float4 q0 = *((const float4*)(sm->enc + l * 256) + lane);
            float4 q1 = *((const float4*)(sm->enc + l * 256) + 32 + lane);
            a0.x += wl*q0.x; a0.y += wl*q0.y; a0.z += wl*q0.z; a0.w += wl*q0.w;
            a1.x += wl*q1.x; a1.y += wl*q1.y; a1.z += wl*q1.z; a1.w += wl*q1.w;
        }
        float sc0 = warp_sum(ce0 + dot4(*((const float4*)wcr0 + 64 + lane), a0) +
                                   dot4(*((const float4*)wcr0 + 96 + lane), a1));
        float sc1 = warp_sum(ce1 + dot4(*((const float4*)wcr1 + 64 + lane), a0) +
                                   dot4(*((const float4*)wcr1 + 96 + lane), a1));
        sc0 = fmaxf(sc0 + bc0, 0.f);
        sc1 = fmaxf(sc1 + bc1, 0.f);
        if (lane < 16) st_cluster(smem_u32(&sm->comb[e0i]), lane, sc0);
        else           st_cluster(smem_u32(&sm->comb[e1i]), lane - 16, sc1);
    }
    csync();                                                  // ---- cs3 (comb)

    // ---- P4: gi (smem) + fused GRU ------------------------------------------
    mbar_wait(&sm->mb2);                                      // wih landed
    {
        float4 c0 = *((const float4*)sm->comb + lane);
        float4 c1 = *((const float4*)sm->comb + 32 + lane);
        float gi[6];
#pragma unroll
        for (int r = 0; r < 6; r++) {
            const int g = r % 3, e = r / 3;
            const float* w = &sm->wih[((g * 2 + e) * NW + wrp) * 256];
            gi[r] = warp_sum(dot4(*((const float4*)w + lane), c0) +
                             dot4(*((const float4*)w + 32 + lane), c1)) + bi6[r];
        }
#pragma unroll
        for (int e = 0; e < 2; e++) {
            const int o = e ? e1i : e0i;
            float h0o = head ? (e ? h01 : h00) : (e ? h_e1 : h_e0);
            float r = 1.f / (1.f + expf(-(gi[e * 3 + 0] + ghv[e * 3 + 0])));
            float z = 1.f / (1.f + expf(-(gi[e * 3 + 1] + ghv[e * 3 + 1])));
            float n = tanhf(gi[e * 3 + 2] + r * ghv[e * 3 + 2]);
            float h = (1.f - z) * n + z * h0o;
            if (lane == 0) {
                st_cluster(smem_u32(&sm->hnew[o]), 0, h);     // to CTA0 only
                out[29 + o] = h;
            }
        }
    }
    // prefetch P5 weights (CTA0) while others finish
    float4 wo[4][2]; float bo[4];
    if (bx == 0) {
#pragma unroll
        for (int r = 0; r < 4; r++) {
            const int o = wrp + r * NW;
            if (o < 29) {
                const float* w = w_out + o * 256;
                wo[r][0] = __ldg((const float4*)w + lane);
                wo[r][1] = __ldg((const float4*)w + 32 + lane);
                bo[r] = __ldg(b_out + o);
            }
        }
    }
    csync();                                                  // ---- cs4 (hnew)
    if (bx != 0) return;

    // ---- P5 (CTA0): output logits + log_softmax -----------------------------
    {
        float4 H0 = *((const float4*)sm->hnew + lane);
        float4 H1 = *((const float4*)sm->hnew + 32 + lane);
#pragma unroll
        for (int r = 0; r < 4; r++) {
            const int o = wrp + r * NW;
            if (o < 29) {
                float s = warp_sum(dot4(wo[r][0], H0) + dot4(wo[r][1], H1)) + bo[r];
                if (lane == 0) sm->olog[o] = s;
            }
        }
    }
    __syncthreads();
    if (wrp == 0) {
        float v = (lane < 29) ? sm->olog[lane] : -1e30f;
        float m = warp_max(v);
        float e = (lane < 29) ? expf(v - m) : 0.f;
        float sum = warp_sum(e);
        float ls = logf(sum);
        if (lane < 29) out[lane] = v - m - ls;
    }
}

// ---------------- launch --------------------------------------------------------
extern "C" void kernel_launch(void* const* d_in, const int* in_sizes, int n_in,
                              void* d_out, int out_size) {
    (void)in_sizes; (void)n_in; (void)out_size;
    cudaFuncSetAttribute(decoder_k, cudaFuncAttributeNonPortableClusterSizeAllowed, 1);
    cudaFuncSetAttribute(decoder_k, cudaFuncAttributeMaxDynamicSharedMemorySize,
                         (int)sizeof(Smem));

    cudaLaunchAttribute at[1];
    at[0].id = cudaLaunchAttributeClusterDimension;
    at[0].val.clusterDim = {CTAS, 1, 1};

    cudaLaunchConfig_t cfg = {};
    cfg.gridDim  = {CTAS, 1, 1};
    cfg.blockDim = {NTHR, 1, 1};
    cfg.dynamicSmemBytes = sizeof(Smem);
    cfg.attrs = at;
    cfg.numAttrs = 1;

    cudaLaunchKernelEx(&cfg, decoder_k,
                       (const int*)d_in[0],  (const float*)d_in[1], (const float*)d_in[2],
                       (const int*)d_in[3],  (const int*)d_in[4],   (const float*)d_in[5],
                       (const float*)d_in[6],(const float*)d_in[7], (const float*)d_in[8],
                       (const float*)d_in[9],(const float*)d_in[10],(const float*)d_in[11],
                       (const float*)d_in[12],(const float*)d_in[13],(const float*)d_in[14],
                       (const float*)d_in[15],(const float*)d_in[16],(const float*)d_in[17],
                       (float*)d_out);
}

// round 11
// speedup vs baseline: 1.5598x; 1.1633x over previous
#include <cuda_runtime.h>
#include <cstdint>
#include <math.h>

#define CTAS 16
#define NTHR 256
#define NW   8      // warps per CTA; CTAS*NW = 128 global warps, 2 elems/warp

// ---------------- dynamic smem layout ------------------------------------------
struct __align__(16) Smem {
    float emb [29 * 256];       // 29696 B  (mbA)
    float wl2d[2 * NW * 264];   // 16896 B  (mbA)
    float hid [256];            //  1024 B  (mbA)
    float whh [6 * NW * 256];   // 49152 B  (mbB)
    float enc [20 * 256];       // 20480 B  (mbB)
    float wcmb[2 * NW * 512];   // 32768 B  (mbC)
    float wih [6 * NW * 256];   // 49152 B  (mbC)
    float h0[256];
    float comb[256];
    float hnew[256];
    float logit[32];
    float olog[32];
    unsigned long long mbA, mbB, mbC, mbH;
};

// ---------------- helpers ------------------------------------------------------
__device__ __forceinline__ float warp_sum(float v) {
#pragma unroll
    for (int o = 16; o; o >>= 1) v += __shfl_xor_sync(0xffffffffu, v, o);
    return v;
}
__device__ __forceinline__ float warp_max(float v) {
#pragma unroll
    for (int o = 16; o; o >>= 1) v = fmaxf(v, __shfl_xor_sync(0xffffffffu, v, o));
    return v;
}
__device__ __forceinline__ float dot4(float4 a, float4 b) {
    return a.x * b.x + a.y * b.y + a.z * b.z + a.w * b.w;
}
__device__ __forceinline__ uint32_t smem_u32(const void* p) {
    uint32_t a;
    asm("{.reg .u64 t; cvta.to.shared.u64 t,%1; cvt.u32.u64 %0,t;}" : "=r"(a) : "l"(p));
    return a;
}
__device__ __forceinline__ void st_cluster(uint32_t laddr, int rank, float v) {
    uint32_t ra;
    asm("mapa.shared::cluster.u32 %0,%1,%2;" : "=r"(ra) : "r"(laddr), "r"(rank));
    asm volatile("st.shared::cluster.f32 [%0],%1;" :: "r"(ra), "f"(v) : "memory");
}
__device__ __forceinline__ void csync() {
    asm volatile("barrier.cluster.arrive.aligned;" ::: "memory");
    asm volatile("barrier.cluster.wait.aligned;" ::: "memory");
}
__device__ __forceinline__ void mbar_init(void* p, unsigned cnt) {
    asm volatile("mbarrier.init.shared.b64 [%0],%1;" :: "r"(smem_u32(p)), "r"(cnt) : "memory");
}
__device__ __forceinline__ void mbar_expect(void* p, unsigned bytes) {
    asm volatile("mbarrier.arrive.expect_tx.shared.b64 _,[%0],%1;"
                 :: "r"(smem_u32(p)), "r"(bytes) : "memory");
}
__device__ __forceinline__ void bulk_g2s(void* dst, const void* src, unsigned bytes, void* mbar) {
    asm volatile("cp.async.bulk.shared::cta.global.mbarrier::complete_tx::bytes [%0],[%1],%2,[%3];"
                 :: "r"(smem_u32(dst)), "l"(src), "r"(bytes), "r"(smem_u32(mbar)) : "memory");
}
__device__ __forceinline__ void mbar_wait(void* p) {
    uint32_t la = smem_u32(p);
    asm volatile(
        "{\n\t.reg .pred P;\n"
        "W%=:\n\t"
        "mbarrier.try_wait.parity.shared.b64 P,[%0],0;\n\t"
        "@!P bra W%=;\n\t}"
        :: "r"(la) : "memory");
}
// release-scope remote arrive on CTA0's mbH
__device__ __forceinline__ void mbar_arrive_cta0(void* p) {
    uint32_t la = smem_u32(p), ra;
    asm("mapa.shared::cluster.u32 %0,%1,%2;" : "=r"(ra) : "r"(la), "r"(0));
    asm volatile("mbarrier.arrive.release.cluster.shared::cluster.b64 _,[%0];"
                 :: "r"(ra) : "memory");
}
__device__ __forceinline__ void mbar_wait_acq(void* p) {
    uint32_t la = smem_u32(p);
    asm volatile(
        "{\n\t.reg .pred P;\n"
        "W%=:\n\t"
        "mbarrier.try_wait.parity.acquire.cluster.shared::cta.b64 P,[%0],0;\n\t"
        "@!P bra W%=;\n\t}"
        :: "r"(la) : "memory");
}
__device__ __forceinline__ float fsig(float x) {
    return __fdividef(1.f, 1.f + __expf(-x));
}

// ---------------- fused decoder step -------------------------------------------
__global__ void __launch_bounds__(NTHR, 1)
decoder_k(const int* __restrict__ inp,
          const float* __restrict__ hidden,   // [256]
          const float* __restrict__ enc,      // [20,256]
          const int* __restrict__ cond,       // [2]
          const int* __restrict__ is_head,    // [1]
          const float* __restrict__ emb,      // [29,256]
          const float* __restrict__ w_l2d,    // [256,264]
          const float* __restrict__ b_l2d,
          const float* __restrict__ w_attn,   // [20,512]
          const float* __restrict__ b_attn,
          const float* __restrict__ w_comb,   // [256,512]
          const float* __restrict__ b_comb,
          const float* __restrict__ w_ih,     // [768,256]
          const float* __restrict__ w_hh,     // [768,256]
          const float* __restrict__ b_ih,
          const float* __restrict__ b_hh,
          const float* __restrict__ w_out,    // [29,256]
          const float* __restrict__ b_out,
          float* __restrict__ out)            // [305]
{
    extern __shared__ Smem sm[];

    const int tid  = threadIdx.x;
    const int lane = tid & 31;
    const int wrp  = tid >> 5;                // 0..7
    const int bx   = blockIdx.x;
    const int gw   = bx * NW + wrp;           // 0..127
    const int e0i  = gw, e1i = gw + 128;

    // ---- t=0: mbarrier init + priority-split bulk copies --------------------
    if (tid == 0) {
        mbar_init(&sm->mbA, 1);
        mbar_init(&sm->mbB, 1);
        mbar_init(&sm->mbC, 1);
        mbar_init(&sm->mbH, CTAS);
    }
    __syncthreads();
    if (tid == 0) {
        // group A: P1 inputs (46.6 KB)
        mbar_expect(&sm->mbA, 29696u + 16896u + 1024u);
        bulk_g2s(sm->emb, emb, 29696u, &sm->mbA);
#pragma unroll
        for (int e = 0; e < 2; e++)
            bulk_g2s(&sm->wl2d[e * NW * 264], w_l2d + (e * 128 + bx * NW) * 264,
                     NW * 264 * 4u, &sm->mbA);
        bulk_g2s(sm->hid, hidden, 1024u, &sm->mbA);
        // group B: P2 inputs (68 KB)
        mbar_expect(&sm->mbB, 49152u + 20480u);
#pragma unroll
        for (int c = 0; c < 6; c++) {         // c = g*2+e
            int g = c >> 1, e = c & 1;
            bulk_g2s(&sm->whh[c * NW * 256], w_hh + (g * 256 + e * 128 + bx * NW) * 256,
                     NW * 256 * 4u, &sm->mbB);
        }
        bulk_g2s(sm->enc, enc, 20480u, &sm->mbB);
        // group C: P3/P4 inputs (80 KB)
        mbar_expect(&sm->mbC, 32768u + 49152u);
#pragma unroll
        for (int e = 0; e < 2; e++)
            bulk_g2s(&sm->wcmb[e * NW * 512], w_comb + (e * 128 + bx * NW) * 512,
                     NW * 512 * 4u, &sm->mbC);
#pragma unroll
        for (int c = 0; c < 6; c++) {
            int g = c >> 1, e = c & 1;
            bulk_g2s(&sm->wih[c * NW * 256], w_ih + (g * 256 + e * 128 + bx * NW) * 256,
                     NW * 256 * 4u, &sm->mbC);
        }
    }

    // ---- small LDGs (overlap with bulk flight) ------------------------------
    const int head = __ldg(is_head);
    const int iv   = __ldg(inp);
    int c0i = __ldg(cond), c1i = __ldg(cond + 1);
    float bh6[6], bi6[6];
#pragma unroll
    for (int r = 0; r < 6; r++) {
        const int o = (r % 3) * 256 + (r < 3 ? e0i : e1i);
        bh6[r] = __ldg(b_hh + o);
        bi6[r] = __ldg(b_ih + o);
    }
    float bc0 = __ldg(b_comb + e0i), bc1 = __ldg(b_comb + e1i);
    float bl0 = __ldg(b_l2d + e0i),  bl1 = __ldg(b_l2d + e1i);
    // distributed attention row (warp gw<20 owns row gw)
    float4 wa[4]; float ba = 0.f;
    if (gw < 20) {
        const float* w = w_attn + gw * 512;
#pragma unroll
        for (int k = 0; k < 4; k++) wa[k] = __ldg((const float4*)w + k * 32 + lane);
        ba = __ldg(b_attn + gw);
    }

    mbar_wait(&sm->mbA);                                      // group A landed

    // ---- P1: h0 rows (head path, all operands in smem) ----------------------
    const float* erow = &sm->emb[iv * 256];
    float4 e0 = *((const float4*)erow + lane);
    float4 e1 = *((const float4*)erow + 32 + lane);
    float4 hx0 = *((const float4*)sm->hid + lane);
    float4 hx1 = *((const float4*)sm->hid + 32 + lane);
    float  h_e0 = sm->hid[e0i], h_e1 = sm->hid[e1i];

    float h00 = 0.f, h01 = 0.f;
    if (head) {
#pragma unroll
        for (int e = 0; e < 2; e++) {
            const float* wr = &sm->wl2d[(e * NW + wrp) * 264];
            float s = dot4(*((const float4*)wr + lane), hx0) +
                      dot4(*((const float4*)(wr + 128) + lane), hx1);
            if (lane < 8) {
                float xv = (lane == c0i || lane == 4 + c1i) ? 1.f : 0.f;
                s += wr[256 + lane] * xv;
            }
            s = warp_sum(s) + (e ? bl1 : bl0);
            if (e) h01 = s; else h00 = s;
        }
        if (lane < 16) st_cluster(smem_u32(&sm->h0[e0i]), lane, h00);
        else           st_cluster(smem_u32(&sm->h0[e1i]), lane - 16, h01);
    }
    csync();                                                  // ---- cs1 (h0)

    // ---- P2: gh + distributed attn logits -----------------------------------
    mbar_wait(&sm->mbB);                                      // whh + enc landed
    float4 x0, x1;
    if (head) { x0 = *((const float4*)sm->h0 + lane); x1 = *((const float4*)sm->h0 + 32 + lane); }
    else      { x0 = hx0; x1 = hx1; }
    float ghv[6];
#pragma unroll
    for (int r = 0; r < 6; r++) {
        const int g = r % 3, e = r / 3;
        const float* w = &sm->whh[((g * 2 + e) * NW + wrp) * 256];
        ghv[r] = warp_sum(dot4(*((const float4*)w + lane), x0) +
                          dot4(*((const float4*)w + 32 + lane), x1)) + bh6[r];
    }
    if (gw < 20) {
        float s = warp_sum(dot4(wa[0], e0) + dot4(wa[1], e1) +
                           dot4(wa[2], x0) + dot4(wa[3], x1)) + ba;
        if (lane < CTAS) st_cluster(smem_u32(&sm->logit[gw]), lane, s);
    }
    csync();                                                  // ---- cs2 (logits)

    // ---- P3: softmax + attn_applied + comb (wcmb from mbC) ------------------
    mbar_wait(&sm->mbC);
    {
        const float* wcr0 = &sm->wcmb[wrp * 512];
        const float* wcr1 = &sm->wcmb[(NW + wrp) * 512];
        float ce0 = dot4(*((const float4*)wcr0 + lane), e0) +
                    dot4(*((const float4*)wcr0 + 32 + lane), e1);
        float ce1 = dot4(*((const float4*)wcr1 + lane), e0) +
                    dot4(*((const float4*)wcr1 + 32 + lane), e1);
        float v = (lane < 20) ? sm->logit[lane] : -1e30f;
        float m = warp_max(v);
        float ex = (lane < 20) ? __expf(v - m) : 0.f;
        float sum = warp_sum(ex);
        float w = __fdividef(ex, sum);
        if (gw == 0 && lane < 20) out[285 + lane] = w;
        float4 a0 = {0.f,0.f,0.f,0.f}, a1 = {0.f,0.f,0.f,0.f};
#pragma unroll
        for (int l = 0; l < 20; l++) {
            float wl = __shfl_sync(0xffffffffu, w, l);
            float4 q0 = *((const float4*)(sm->enc + l * 256) + lane);
            float4 q1 = *((const float4*)(sm->enc + l * 256) + 32 + lane);
            a0.x += wl*q0.x; a0.y += wl*q0.y; a0.z += wl*q0.z; a0.w += wl*q0.w;
            a1.x += wl*q1.x; a1.y += wl*q1.y; a1.z += wl*q1.z; a1.w += wl*q1.w;
        }
        float sc0 = warp_sum(ce0 + dot4(*((const float4*)wcr0 + 64 + lane), a0) +
                                   dot4(*((const float4*)wcr0 + 96 + lane), a1));
        float sc1 = warp_sum(ce1 + dot4(*((const float4*)wcr1 + 64 + lane), a0) +
                                   dot4(*((const float4*)wcr1 + 96 + lane), a1));
        sc0 = fmaxf(sc0 + bc0, 0.f);
        sc1 = fmaxf(sc1 + bc1, 0.f);
        if (lane < 16) st_cluster(smem_u32(&sm->comb[e0i]), lane, sc0);
        else           st_cluster(smem_u32(&sm->comb[e1i]), lane - 16, sc1);
    }
    csync();                                                  // ---- cs3 (comb)

    // ---- P4: gi + fused GRU --------------------------------------------------
    {
        float4 c0 = *((const float4*)sm->comb + lane);
        float4 c1 = *((const float4*)sm->comb + 32 + lane);
        float gi[6];
#pragma unroll
        for (int r = 0; r < 6; r++) {
            const int g = r % 3, e = r / 3;
            const float* w = &sm->wih[((g * 2 + e) * NW + wrp) * 256];
            gi[r] = warp_sum(dot4(*((const float4*)w + lane), c0) +
                             dot4(*((const float4*)w + 32 + lane), c1)) + bi6[r];
        }
#pragma unroll
        for (int e = 0; e < 2; e++) {
            const int o = e ? e1i : e0i;
            float h0o = head ? (e ? h01 : h00) : (e ? h_e1 : h_e0);
            float r = fsig(gi[e * 3 + 0] + ghv[e * 3 + 0]);
            float z = fsig(gi[e * 3 + 1] + ghv[e * 3 + 1]);
            float n = 2.f * fsig(2.f * (gi[e * 3 + 2] + r * ghv[e * 3 + 2])) - 1.f;
            float h = (1.f - z) * n + z * h0o;
            if (lane == 0) {
                st_cluster(smem_u32(&sm->hnew[o]), 0, h);     // to CTA0 only
                out[29 + o] = h;
            }
        }
    }
    __syncthreads();
    if (tid == 0) mbar_arrive_cta0(&sm->mbH);                 // light hnew signal
    if (bx != 0) return;                                      // CTAs 1-15 exit

    // prefetch P5 weights while waiting
    float4 wo[4][2]; float bo[4];
#pragma unroll
    for (int r = 0; r < 4; r++) {
        const int o = wrp + r * NW;
        if (o < 29) {
            const float* w = w_out + o * 256;
            wo[r][0] = __ldg((const float4*)w + lane);
            wo[r][1] = __ldg((const float4*)w + 32 + lane);
            bo[r] = __ldg(b_out + o);
        }
    }
    mbar_wait_acq(&sm->mbH);                                  // all hnew landed

    // ---- P5 (CTA0): output logits + log_softmax -----------------------------
    {
        float4 H0 = *((const float4*)sm->hnew + lane);
        float4 H1 = *((const float4*)sm->hnew + 32 + lane);
#pragma unroll
        for (int r = 0; r < 4; r++) {
            const int o = wrp + r * NW;
            if (o < 29) {
                float s = warp_sum(dot4(wo[r][0], H0) + dot4(wo[r][1], H1)) + bo[r];
                if (lane == 0) sm->olog[o] = s;
            }
        }
    }
    __syncthreads();
    if (wrp == 0) {
        float v = (lane < 29) ? sm->olog[lane] : -1e30f;
        float m = warp_max(v);
        float e = (lane < 29) ? __expf(v - m) : 0.f;
        float sum = warp_sum(e);
        float ls = __logf(sum);
        if (lane < 29) out[lane] = v - m - ls;
    }
}

// ---------------- launch --------------------------------------------------------
extern "C" void kernel_launch(void* const* d_in, const int* in_sizes, int n_in,
                              void* d_out, int out_size) {
    (void)in_sizes; (void)n_in; (void)out_size;
    cudaFuncSetAttribute(decoder_k, cudaFuncAttributeNonPortableClusterSizeAllowed, 1);
    cudaFuncSetAttribute(decoder_k, cudaFuncAttributeMaxDynamicSharedMemorySize,
                         (int)sizeof(Smem));

    cudaLaunchAttribute at[1];
    at[0].id = cudaLaunchAttributeClusterDimension;
    at[0].val.clusterDim = {CTAS, 1, 1};

    cudaLaunchConfig_t cfg = {};
    cfg.gridDim  = {CTAS, 1, 1};
    cfg.blockDim = {NTHR, 1, 1};
    cfg.dynamicSmemBytes = sizeof(Smem);
    cfg.attrs = at;
    cfg.numAttrs = 1;

    cudaLaunchKernelEx(&cfg, decoder_k,
                       (const int*)d_in[0],  (const float*)d_in[1], (const float*)d_in[2],
                       (const int*)d_in[3],  (const int*)d_in[4],   (const float*)d_in[5],
                       (const float*)d_in[6],(const float*)d_in[7], (const float*)d_in[8],
                       (const float*)d_in[9],(const float*)d_in[10],(const float*)d_in[11],
                       (const float*)d_in[12],(const float*)d_in[13],(const float*)d_in[14],
                       (const float*)d_in[15],(const float*)d_in[16],(const float*)d_in[17],
                       (float*)d_out);
}